// round 15
// baseline (speedup 1.0000x reference)
#include <cuda_runtime.h>
#include <math.h>

// Pe_i_CrossAttention: fused point-transformer local attention.
// B=4, C=64, N=16384, K=16, H=8, D=8.
// R14/R15: R13 mapping (warp = 4 pts, lane = (p, kh, hh)) + occupancy push:
//   - Wq evicted from smem (pass 1 reads pre-permuted global via __ldg)
//     -> smem 66.8KB -> 49.7KB -> 4 CTAs/SM (32 warps)
//   - __launch_bounds__(256,4) caps regs at 64 (live state ~50)
// energy[h,k] = (Wk_h^T q_h).nb_k ; out[h] = Wv_h @ (sum_k attn_k nb_k)

#define B_      4
#define C_      64
#define N_      16384
#define K_      16
#define CP3     67
#define PTS     32                  // 8 warps x 4 points
#define THREADS 256
#define PC_STRIDE 68
#define SX_STRIDE 52
#define W_ELEMS (CP3 * C_)          // 4288
#define CSTR    ((size_t)N_ * K_)   // float stride between c-rows of neighbors

__device__ __align__(16) float g_WT[3 * W_ELEMS];

// Quad-permuted transpose:
//   source element: W[o*67 + c], o = h*8 + d;  dd = d&3, kh = (d>>2)
//   dest: [c][new_pos][dd], new_pos = (h&1)*8 + (h>>1)*2 + kh
// -> in-kernel instr j (head 2hh+j) reads float4 at c*16 + j*8 + hh*2 + kh:
//    8 unique float4 per instr, contiguous 128B -> 1 conflict-free wavefront.
// 1/sqrt(D) folded into Wq.
__global__ void permute_w_kernel(const float* __restrict__ Wq,
                                 const float* __restrict__ Wk,
                                 const float* __restrict__ Wv)
{
    int e = blockIdx.x * blockDim.x + threadIdx.x;
    if (e >= W_ELEMS) return;
    int c    = e >> 6;
    int t    = e & 63;
    int qidx = t >> 2;              // 0..15
    int dd   = t & 3;
    int h    = qidx >> 1;
    int kh   = qidx & 1;
    int o    = h * 8 + kh * 4 + dd;
    int np   = (h & 1) * 8 + (h >> 1) * 2 + kh;
    int dst  = c * 64 + np * 4 + dd;
    g_WT[dst]               = Wq[o * CP3 + c] * 0.35355339059327373f;
    g_WT[W_ELEMS + dst]     = Wk[o * CP3 + c];
    g_WT[2 * W_ELEMS + dst] = Wv[o * CP3 + c];
}

__global__ __launch_bounds__(THREADS, 4)
void pt_attn_kernel(const float* __restrict__ pcd,
                    const float* __restrict__ neighbors,
                    const float* __restrict__ xyz,
                    const int*   __restrict__ idx_all,
                    float*       __restrict__ out)
{
    __shared__ __align__(16) float sW[2 * W_ELEMS];          // Wk, Wv: 34304 B
    __shared__ float pc[PTS * PC_STRIDE];                    // [32][68]
    __shared__ __align__(16) float sxyz[PTS * SX_STRIDE];    // [32][52] (3x16 used)

    const int tid = threadIdx.x;
    const int g0  = blockIdx.x * PTS;         // 32 | 16384 -> never crosses batch
    const int b   = g0 / N_;
    const int n0  = g0 % N_;

    // ---- Wk/Wv: coalesced float4 copy from pre-permuted global scratch
    {
        const float4* src = (const float4*)(g_WT + W_ELEMS);
        float4*       dst = (float4*)sW;
        for (int e = tid; e < 2 * W_ELEMS / 4; e += THREADS) dst[e] = src[e];
    }
    // ---- center features (coalesced over p, 32-wide)
    for (int e = tid; e < C_ * PTS; e += THREADS) {
        int c = e >> 5, p = e & 31;
        pc[p * PC_STRIDE + c] = pcd[(b * C_ + c) * N_ + n0 + p];
    }
    for (int e = tid; e < 3 * PTS; e += THREADS) {
        int j = e >> 5, p = e & 31;
        pc[p * PC_STRIDE + 64 + j] = xyz[(b * 3 + j) * N_ + n0 + p];
    }
    // ---- gathered xyz rows (xyz is 768 KB -> L2-resident)
    for (int e = tid; e < PTS * K_; e += THREADS) {
        int p = e >> 4, k = e & 15;
        int idx = idx_all[(b * N_ + n0 + p) * K_ + k];
        #pragma unroll
        for (int j = 0; j < 3; j++)
            sxyz[p * SX_STRIDE + j * 16 + k] = xyz[(b * 3 + j) * N_ + idx];
    }
    __syncthreads();

    // ---- lane mapping
    const int lane = tid & 31;
    const int w    = tid >> 5;
    const int p    = lane >> 3;               // point within warp (0..3)
    const int kh   = (lane >> 2) & 1;         // k-half / d-half
    const int hh   = lane & 3;                // head-pair index
    const int pidx = w * 4 + p;
    const int n    = n0 + pidx;
    const int wb   = hh * 2 + kh;             // W float4 sub-offset
    const float*  pcp = pc + pidx * PC_STRIDE;
    const float4* sxp = (const float4*)(sxyz + pidx * SX_STRIDE + kh * 8);
    const float*  nbg = neighbors + ((size_t)(b * C_) * N_ + (size_t)n) * K_ + kh * 8;
    const float4* WqG = (const float4*)g_WT;                  // global (L2-resident)
    const float4* WkT = (const float4*)sW;
    const float4* WvT = (const float4*)(sW + W_ELEMS);

    // ======== pass 1: q[j*4+dd] = q_{2hh+j}[kh*4+dd] (scale pre-folded) ====
    float q[8];
    #pragma unroll
    for (int d = 0; d < 8; d++) q[d] = 0.f;
    #pragma unroll 4
    for (int c = 0; c < CP3; c++) {
        float x = pcp[c];
        float4 w0 = __ldg(WqG + c * 16 + wb);         // head 2hh
        float4 w1 = __ldg(WqG + c * 16 + 8 + wb);     // head 2hh+1
        q[0] = fmaf(w0.x, x, q[0]); q[1] = fmaf(w0.y, x, q[1]);
        q[2] = fmaf(w0.z, x, q[2]); q[3] = fmaf(w0.w, x, q[3]);
        q[4] = fmaf(w1.x, x, q[4]); q[5] = fmaf(w1.y, x, q[5]);
        q[6] = fmaf(w1.z, x, q[6]); q[7] = fmaf(w1.w, x, q[7]);
    }

    // ======== pass 2: energies e[j][k'] over own 8 k for 2 heads ========
    float e0[16];
    #pragma unroll
    for (int k = 0; k < 16; k++) e0[k] = 0.f;
    #pragma unroll 2
    for (int c = 0; c < C_; c++) {
        const float4* nr = (const float4*)(nbg + (size_t)c * CSTR);
        float4 na = nr[0], nbv = nr[1];
        float4 w0 = WkT[c * 16 + wb];
        float4 w1 = WkT[c * 16 + 8 + wb];
        float rp0 = fmaf(w0.x, q[0], w0.y * q[1]);
        float rp1 = fmaf(w1.x, q[4], w1.y * q[5]);
        rp0 = fmaf(w0.z, q[2], rp0); rp1 = fmaf(w1.z, q[6], rp1);
        rp0 = fmaf(w0.w, q[3], rp0); rp1 = fmaf(w1.w, q[7], rp1);
        float r0 = rp0 + __shfl_xor_sync(0xffffffffu, rp0, 4);
        float r1 = rp1 + __shfl_xor_sync(0xffffffffu, rp1, 4);
        e0[0]  = fmaf(r0, na.x, e0[0]);  e0[1]  = fmaf(r0, na.y, e0[1]);
        e0[2]  = fmaf(r0, na.z, e0[2]);  e0[3]  = fmaf(r0, na.w, e0[3]);
        e0[4]  = fmaf(r0, nbv.x, e0[4]); e0[5]  = fmaf(r0, nbv.y, e0[5]);
        e0[6]  = fmaf(r0, nbv.z, e0[6]); e0[7]  = fmaf(r0, nbv.w, e0[7]);
        e0[8]  = fmaf(r1, na.x, e0[8]);  e0[9]  = fmaf(r1, na.y, e0[9]);
        e0[10] = fmaf(r1, na.z, e0[10]); e0[11] = fmaf(r1, na.w, e0[11]);
        e0[12] = fmaf(r1, nbv.x, e0[12]); e0[13] = fmaf(r1, nbv.y, e0[13]);
        e0[14] = fmaf(r1, nbv.z, e0[14]); e0[15] = fmaf(r1, nbv.w, e0[15]);
    }
    #pragma unroll
    for (int j = 0; j < 3; j++) {             // xyz tail rows from smem
        int c = C_ + j;
        float4 na = sxp[j * 4], nbv = sxp[j * 4 + 1];
        float4 w0 = WkT[c * 16 + wb];
        float4 w1 = WkT[c * 16 + 8 + wb];
        float rp0 = fmaf(w0.x, q[0], w0.y * q[1]);
        float rp1 = fmaf(w1.x, q[4], w1.y * q[5]);
        rp0 = fmaf(w0.z, q[2], rp0); rp1 = fmaf(w1.z, q[6], rp1);
        rp0 = fmaf(w0.w, q[3], rp0); rp1 = fmaf(w1.w, q[7], rp1);
        float r0 = rp0 + __shfl_xor_sync(0xffffffffu, rp0, 4);
        float r1 = rp1 + __shfl_xor_sync(0xffffffffu, rp1, 4);
        e0[0]  = fmaf(r0, na.x, e0[0]);  e0[1]  = fmaf(r0, na.y, e0[1]);
        e0[2]  = fmaf(r0, na.z, e0[2]);  e0[3]  = fmaf(r0, na.w, e0[3]);
        e0[4]  = fmaf(r0, nbv.x, e0[4]); e0[5]  = fmaf(r0, nbv.y, e0[5]);
        e0[6]  = fmaf(r0, nbv.z, e0[6]); e0[7]  = fmaf(r0, nbv.w, e0[7]);
        e0[8]  = fmaf(r1, na.x, e0[8]);  e0[9]  = fmaf(r1, na.y, e0[9]);
        e0[10] = fmaf(r1, na.z, e0[10]); e0[11] = fmaf(r1, na.w, e0[11]);
        e0[12] = fmaf(r1, nbv.x, e0[12]); e0[13] = fmaf(r1, nbv.y, e0[13]);
        e0[14] = fmaf(r1, nbv.z, e0[14]); e0[15] = fmaf(r1, nbv.w, e0[15]);
    }

    // ======== softmax per head over 16 k (8 local + kh-partner) ========
    float m0 = e0[0], m1 = e0[8];
    #pragma unroll
    for (int k = 1; k < 8; k++) { m0 = fmaxf(m0, e0[k]); m1 = fmaxf(m1, e0[8 + k]); }
    m0 = fmaxf(m0, __shfl_xor_sync(0xffffffffu, m0, 4));
    m1 = fmaxf(m1, __shfl_xor_sync(0xffffffffu, m1, 4));
    float s0sum = 0.f, s1sum = 0.f;
    #pragma unroll
    for (int k = 0; k < 8; k++) {
        e0[k]     = __expf(e0[k] - m0);     s0sum += e0[k];
        e0[8 + k] = __expf(e0[8 + k] - m1); s1sum += e0[8 + k];
    }
    s0sum += __shfl_xor_sync(0xffffffffu, s0sum, 4);
    s1sum += __shfl_xor_sync(0xffffffffu, s1sum, 4);
    float inv0 = 1.f / s0sum, inv1 = 1.f / s1sum;
    #pragma unroll
    for (int k = 0; k < 8; k++) { e0[k] *= inv0; e0[8 + k] *= inv1; }

    // ======== pass 3: o[j*4+dd] += Wv[c, (2hh+j)*8+kh*4+dd] * s_j ========
    float o[8];
    #pragma unroll
    for (int d = 0; d < 8; d++) o[d] = 0.f;
    #pragma unroll 2
    for (int c = 0; c < C_; c++) {
        const float4* nr = (const float4*)(nbg + (size_t)c * CSTR);
        float4 na = nr[0], nbv = nr[1];
        float sa0 = fmaf(e0[0], na.x, e0[1] * na.y);
        float sb0 = fmaf(e0[2], na.z, e0[3] * na.w);
        float sa1 = fmaf(e0[8], na.x, e0[9] * na.y);
        float sb1 = fmaf(e0[10], na.z, e0[11] * na.w);
        sa0 = fmaf(e0[4], nbv.x, sa0); sb0 = fmaf(e0[5], nbv.y, sb0);
        sa1 = fmaf(e0[12], nbv.x, sa1); sb1 = fmaf(e0[13], nbv.y, sb1);
        sa0 = fmaf(e0[6], nbv.z, sa0); sb0 = fmaf(e0[7], nbv.w, sb0);
        sa1 = fmaf(e0[14], nbv.z, sa1); sb1 = fmaf(e0[15], nbv.w, sb1);
        float sp0 = sa0 + sb0, sp1 = sa1 + sb1;
        float s0 = sp0 + __shfl_xor_sync(0xffffffffu, sp0, 4);
        float s1 = sp1 + __shfl_xor_sync(0xffffffffu, sp1, 4);
        float4 w0 = WvT[c * 16 + wb];
        float4 w1 = WvT[c * 16 + 8 + wb];
        o[0] = fmaf(w0.x, s0, o[0]); o[1] = fmaf(w0.y, s0, o[1]);
        o[2] = fmaf(w0.z, s0, o[2]); o[3] = fmaf(w0.w, s0, o[3]);
        o[4] = fmaf(w1.x, s1, o[4]); o[5] = fmaf(w1.y, s1, o[5]);
        o[6] = fmaf(w1.z, s1, o[6]); o[7] = fmaf(w1.w, s1, o[7]);
    }
    #pragma unroll
    for (int j = 0; j < 3; j++) {
        int c = C_ + j;
        float4 na = sxp[j * 4], nbv = sxp[j * 4 + 1];
        float sa0 = fmaf(e0[0], na.x, e0[1] * na.y);
        float sb0 = fmaf(e0[2], na.z, e0[3] * na.w);
        float sa1 = fmaf(e0[8], na.x, e0[9] * na.y);
        float sb1 = fmaf(e0[10], na.z, e0[11] * na.w);
        sa0 = fmaf(e0[4], nbv.x, sa0); sb0 = fmaf(e0[5], nbv.y, sb0);
        sa1 = fmaf(e0[12], nbv.x, sa1); sb1 = fmaf(e0[13], nbv.y, sb1);
        sa0 = fmaf(e0[6], nbv.z, sa0); sb0 = fmaf(e0[7], nbv.w, sb0);
        sa1 = fmaf(e0[14], nbv.z, sa1); sb1 = fmaf(e0[15], nbv.w, sb1);
        float sp0 = sa0 + sb0, sp1 = sa1 + sb1;
        float s0 = sp0 + __shfl_xor_sync(0xffffffffu, sp0, 4);
        float s1 = sp1 + __shfl_xor_sync(0xffffffffu, sp1, 4);
        float4 w0 = WvT[c * 16 + wb];
        float4 w1 = WvT[c * 16 + 8 + wb];
        o[0] = fmaf(w0.x, s0, o[0]); o[1] = fmaf(w0.y, s0, o[1]);
        o[2] = fmaf(w0.z, s0, o[2]); o[3] = fmaf(w0.w, s0, o[3]);
        o[4] = fmaf(w1.x, s1, o[4]); o[5] = fmaf(w1.y, s1, o[5]);
        o[6] = fmaf(w1.z, s1, o[6]); o[7] = fmaf(w1.w, s1, o[7]);
    }

    // ---- store: out[b, (2hh+j)*8 + kh*4 + dd, n]
    {
        float* ob0 = out + ((size_t)(b * C_ + (2 * hh) * 8 + kh * 4)) * N_ + n;
        float* ob1 = out + ((size_t)(b * C_ + (2 * hh + 1) * 8 + kh * 4)) * N_ + n;
        #pragma unroll
        for (int dd = 0; dd < 4; dd++) {
            ob0[(size_t)dd * N_] = o[dd];
            ob1[(size_t)dd * N_] = o[4 + dd];
        }
    }
}

extern "C" void kernel_launch(void* const* d_in, const int* in_sizes, int n_in,
                              void* d_out, int out_size)
{
    (void)in_sizes; (void)n_in; (void)out_size;
    const float* pcd       = (const float*)d_in[0];
    const float* neighbors = (const float*)d_in[1];
    const float* xyz       = (const float*)d_in[2];
    const float* Wq        = (const float*)d_in[3];
    const float* Wk        = (const float*)d_in[4];
    const float* Wv        = (const float*)d_in[5];
    const int*   idx_all   = (const int*)d_in[6];
    float* out = (float*)d_out;

    permute_w_kernel<<<(W_ELEMS + 255) / 256, 256>>>(Wq, Wk, Wv);

    const int grid = (B_ * N_) / PTS;   // 2048
    pt_attn_kernel<<<grid, THREADS>>>(pcd, neighbors, xyz, idx_all, out);
}

// round 16
// speedup vs baseline: 1.1104x; 1.1104x over previous
#include <cuda_runtime.h>
#include <math.h>

// Pe_i_CrossAttention: fused point-transformer local attention.
// B=4, C=64, N=16384, K=16, H=8, D=8.
// R16: R13 base (warp = 4 pts, lane = (p, kh, hh), 3 CTAs/SM, W in smem
// quad-permuted) + packed f32x2 FMA (FFMA2, PTX-only) in all hot loops:
// ~25-30% fewer issue slots per c, identical fp32 numerics.
// energy[h,k] = (Wk_h^T q_h).nb_k ; out[h] = Wv_h @ (sum_k attn_k nb_k)

#define B_      4
#define C_      64
#define N_      16384
#define K_      16
#define CP3     67
#define PTS     32                  // 8 warps x 4 points
#define THREADS 256
#define PC_STRIDE 68
#define SX_STRIDE 52
#define W_ELEMS (CP3 * C_)          // 4288
#define CSTR    ((size_t)N_ * K_)   // float stride between c-rows of neighbors

typedef unsigned long long f32x2_t;

__device__ __forceinline__ f32x2_t pk2(float lo, float hi) {
    f32x2_t r; asm("mov.b64 %0, {%1, %2};" : "=l"(r) : "f"(lo), "f"(hi)); return r;
}
__device__ __forceinline__ void upk2(f32x2_t a, float& lo, float& hi) {
    asm("mov.b64 {%0, %1}, %2;" : "=f"(lo), "=f"(hi) : "l"(a));
}
__device__ __forceinline__ f32x2_t fma2(f32x2_t a, f32x2_t b, f32x2_t c) {
    f32x2_t d; asm("fma.rn.f32x2 %0, %1, %2, %3;" : "=l"(d) : "l"(a), "l"(b), "l"(c));
    return d;
}
__device__ __forceinline__ f32x2_t mul2(f32x2_t a, f32x2_t b) {
    f32x2_t d; asm("mul.rn.f32x2 %0, %1, %2;" : "=l"(d) : "l"(a), "l"(b));
    return d;
}
__device__ __forceinline__ float hsum2(f32x2_t a) {
    float x, y; upk2(a, x, y); return x + y;
}

__device__ __align__(16) float g_WT[3 * W_ELEMS];

// Quad-permuted transpose:
//   source element: W[o*67 + c], o = h*8 + d;  dd = d&3, kh = (d>>2)
//   dest: [c][new_pos][dd], new_pos = (h&1)*8 + (h>>1)*2 + kh
// -> in-kernel instr j (head 2hh+j) reads float4 at c*16 + j*8 + hh*2 + kh:
//    8 unique float4 per instr, contiguous 128B -> 1 conflict-free wavefront.
// 1/sqrt(D) folded into Wq.
__global__ void permute_w_kernel(const float* __restrict__ Wq,
                                 const float* __restrict__ Wk,
                                 const float* __restrict__ Wv)
{
    int e = blockIdx.x * blockDim.x + threadIdx.x;
    if (e >= W_ELEMS) return;
    int c    = e >> 6;
    int t    = e & 63;
    int qidx = t >> 2;              // 0..15
    int dd   = t & 3;
    int h    = qidx >> 1;
    int kh   = qidx & 1;
    int o    = h * 8 + kh * 4 + dd;
    int np   = (h & 1) * 8 + (h >> 1) * 2 + kh;
    int dst  = c * 64 + np * 4 + dd;
    g_WT[dst]               = Wq[o * CP3 + c] * 0.35355339059327373f;
    g_WT[W_ELEMS + dst]     = Wk[o * CP3 + c];
    g_WT[2 * W_ELEMS + dst] = Wv[o * CP3 + c];
}

__global__ __launch_bounds__(THREADS, 3)
void pt_attn_kernel(const float* __restrict__ pcd,
                    const float* __restrict__ neighbors,
                    const float* __restrict__ xyz,
                    const int*   __restrict__ idx_all,
                    float*       __restrict__ out)
{
    __shared__ __align__(16) float sW[3 * W_ELEMS];          // 51456 B
    __shared__ float pc[PTS * PC_STRIDE];                    // [32][68]
    __shared__ __align__(16) float sxyz[PTS * SX_STRIDE];    // [32][52] (3x16 used)

    const int tid = threadIdx.x;
    const int g0  = blockIdx.x * PTS;         // 32 | 16384 -> never crosses batch
    const int b   = g0 / N_;
    const int n0  = g0 % N_;

    // ---- W: coalesced float4 copy from pre-permuted global scratch
    {
        const float4* src = (const float4*)g_WT;
        float4*       dst = (float4*)sW;
        for (int e = tid; e < 3 * W_ELEMS / 4; e += THREADS) dst[e] = src[e];
    }
    // ---- center features (coalesced over p, 32-wide)
    for (int e = tid; e < C_ * PTS; e += THREADS) {
        int c = e >> 5, p = e & 31;
        pc[p * PC_STRIDE + c] = pcd[(b * C_ + c) * N_ + n0 + p];
    }
    for (int e = tid; e < 3 * PTS; e += THREADS) {
        int j = e >> 5, p = e & 31;
        pc[p * PC_STRIDE + 64 + j] = xyz[(b * 3 + j) * N_ + n0 + p];
    }
    // ---- gathered xyz rows (xyz is 768 KB -> L2-resident)
    for (int e = tid; e < PTS * K_; e += THREADS) {
        int p = e >> 4, k = e & 15;
        int idx = idx_all[(b * N_ + n0 + p) * K_ + k];
        #pragma unroll
        for (int j = 0; j < 3; j++)
            sxyz[p * SX_STRIDE + j * 16 + k] = xyz[(b * 3 + j) * N_ + idx];
    }
    __syncthreads();

    // ---- lane mapping
    const int lane = tid & 31;
    const int w    = tid >> 5;
    const int p    = lane >> 3;               // point within warp (0..3)
    const int kh   = (lane >> 2) & 1;         // k-half / d-half
    const int hh   = lane & 3;                // head-pair index
    const int pidx = w * 4 + p;
    const int n    = n0 + pidx;
    const int wb   = hh * 2 + kh;             // W float4 sub-offset
    const float*  pcp = pc + pidx * PC_STRIDE;
    const float4* sxp = (const float4*)(sxyz + pidx * SX_STRIDE + kh * 8);
    const float*  nbg = neighbors + ((size_t)(b * C_) * N_ + (size_t)n) * K_ + kh * 8;
    const float4* WqT = (const float4*)sW;                    // [c][16] float4
    const float4* WkT = (const float4*)(sW + W_ELEMS);
    const float4* WvT = (const float4*)(sW + 2 * W_ELEMS);

    // ======== pass 1: q (packed pairs; scale pre-folded) ========
    // Q01/Q23 = head 2hh dims (kh*4 +0..3), Q45/Q67 = head 2hh+1.
    f32x2_t Q01 = 0, Q23 = 0, Q45 = 0, Q67 = 0;
    #pragma unroll 4
    for (int c = 0; c < CP3; c++) {
        float x = pcp[c];
        f32x2_t X = pk2(x, x);
        float4 w0 = WqT[c * 16 + wb];
        float4 w1 = WqT[c * 16 + 8 + wb];
        Q01 = fma2(pk2(w0.x, w0.y), X, Q01);
        Q23 = fma2(pk2(w0.z, w0.w), X, Q23);
        Q45 = fma2(pk2(w1.x, w1.y), X, Q45);
        Q67 = fma2(pk2(w1.z, w1.w), X, Q67);
    }

    // ======== pass 2: energies (packed) over own 8 k for 2 heads ========
    // E[0..3]: head0 k-pairs (k0k1,k2k3,k4k5,k6k7); E[4..7]: head1.
    f32x2_t E[8];
    #pragma unroll
    for (int k = 0; k < 8; k++) E[k] = 0;
    #pragma unroll 2
    for (int c = 0; c < C_; c++) {
        const float4* nr = (const float4*)(nbg + (size_t)c * CSTR);
        float4 na = nr[0], nbv = nr[1];
        float4 w0 = WkT[c * 16 + wb];
        float4 w1 = WkT[c * 16 + 8 + wb];
        float rp0 = hsum2(fma2(pk2(w0.z, w0.w), Q23, mul2(pk2(w0.x, w0.y), Q01)));
        float rp1 = hsum2(fma2(pk2(w1.z, w1.w), Q67, mul2(pk2(w1.x, w1.y), Q45)));
        float r0 = rp0 + __shfl_xor_sync(0xffffffffu, rp0, 4);
        float r1 = rp1 + __shfl_xor_sync(0xffffffffu, rp1, 4);
        f32x2_t R0 = pk2(r0, r0), R1 = pk2(r1, r1);
        f32x2_t A0 = pk2(na.x, na.y),  A1 = pk2(na.z, na.w);
        f32x2_t A2 = pk2(nbv.x, nbv.y), A3 = pk2(nbv.z, nbv.w);
        E[0] = fma2(R0, A0, E[0]); E[1] = fma2(R0, A1, E[1]);
        E[2] = fma2(R0, A2, E[2]); E[3] = fma2(R0, A3, E[3]);
        E[4] = fma2(R1, A0, E[4]); E[5] = fma2(R1, A1, E[5]);
        E[6] = fma2(R1, A2, E[6]); E[7] = fma2(R1, A3, E[7]);
    }
    #pragma unroll
    for (int j = 0; j < 3; j++) {             // xyz tail rows from smem
        int c = C_ + j;
        float4 na = sxp[j * 4], nbv = sxp[j * 4 + 1];
        float4 w0 = WkT[c * 16 + wb];
        float4 w1 = WkT[c * 16 + 8 + wb];
        float rp0 = hsum2(fma2(pk2(w0.z, w0.w), Q23, mul2(pk2(w0.x, w0.y), Q01)));
        float rp1 = hsum2(fma2(pk2(w1.z, w1.w), Q67, mul2(pk2(w1.x, w1.y), Q45)));
        float r0 = rp0 + __shfl_xor_sync(0xffffffffu, rp0, 4);
        float r1 = rp1 + __shfl_xor_sync(0xffffffffu, rp1, 4);
        f32x2_t R0 = pk2(r0, r0), R1 = pk2(r1, r1);
        f32x2_t A0 = pk2(na.x, na.y),  A1 = pk2(na.z, na.w);
        f32x2_t A2 = pk2(nbv.x, nbv.y), A3 = pk2(nbv.z, nbv.w);
        E[0] = fma2(R0, A0, E[0]); E[1] = fma2(R0, A1, E[1]);
        E[2] = fma2(R0, A2, E[2]); E[3] = fma2(R0, A3, E[3]);
        E[4] = fma2(R1, A0, E[4]); E[5] = fma2(R1, A1, E[5]);
        E[6] = fma2(R1, A2, E[6]); E[7] = fma2(R1, A3, E[7]);
    }

    // ======== softmax per head over 16 k (8 local + kh-partner) ========
    float e0[16];
    #pragma unroll
    for (int k = 0; k < 8; k++) upk2(E[k], e0[2 * k], e0[2 * k + 1]);
    float m0 = e0[0], m1 = e0[8];
    #pragma unroll
    for (int k = 1; k < 8; k++) { m0 = fmaxf(m0, e0[k]); m1 = fmaxf(m1, e0[8 + k]); }
    m0 = fmaxf(m0, __shfl_xor_sync(0xffffffffu, m0, 4));
    m1 = fmaxf(m1, __shfl_xor_sync(0xffffffffu, m1, 4));
    float s0sum = 0.f, s1sum = 0.f;
    #pragma unroll
    for (int k = 0; k < 8; k++) {
        e0[k]     = __expf(e0[k] - m0);     s0sum += e0[k];
        e0[8 + k] = __expf(e0[8 + k] - m1); s1sum += e0[8 + k];
    }
    s0sum += __shfl_xor_sync(0xffffffffu, s0sum, 4);
    s1sum += __shfl_xor_sync(0xffffffffu, s1sum, 4);
    float inv0 = 1.f / s0sum, inv1 = 1.f / s1sum;
    #pragma unroll
    for (int k = 0; k < 8; k++) { e0[k] *= inv0; e0[8 + k] *= inv1; }
    // repack attn in the same pair layout as A0..A3
    f32x2_t P[8];
    #pragma unroll
    for (int k = 0; k < 8; k++) P[k] = pk2(e0[2 * k], e0[2 * k + 1]);

    // ======== pass 3: o (packed) += Wv * s, s via partner shuffle ========
    // O[0]=head0 dims 0,1; O[1]=head0 dims 2,3; O[2]/O[3]=head1. (dims = kh-half)
    f32x2_t O[4];
    #pragma unroll
    for (int d = 0; d < 4; d++) O[d] = 0;
    #pragma unroll 2
    for (int c = 0; c < C_; c++) {
        const float4* nr = (const float4*)(nbg + (size_t)c * CSTR);
        float4 na = nr[0], nbv = nr[1];
        f32x2_t A0 = pk2(na.x, na.y),  A1 = pk2(na.z, na.w);
        f32x2_t A2 = pk2(nbv.x, nbv.y), A3 = pk2(nbv.z, nbv.w);
        f32x2_t t0 = fma2(P[1], A1, mul2(P[0], A0));
        f32x2_t u0 = fma2(P[3], A3, mul2(P[2], A2));
        f32x2_t t1 = fma2(P[5], A1, mul2(P[4], A0));
        f32x2_t u1 = fma2(P[7], A3, mul2(P[6], A2));
        float sp0 = hsum2(t0) + hsum2(u0);
        float sp1 = hsum2(t1) + hsum2(u1);
        float s0 = sp0 + __shfl_xor_sync(0xffffffffu, sp0, 4);
        float s1 = sp1 + __shfl_xor_sync(0xffffffffu, sp1, 4);
        f32x2_t S0 = pk2(s0, s0), S1 = pk2(s1, s1);
        float4 w0 = WvT[c * 16 + wb];
        float4 w1 = WvT[c * 16 + 8 + wb];
        O[0] = fma2(pk2(w0.x, w0.y), S0, O[0]);
        O[1] = fma2(pk2(w0.z, w0.w), S0, O[1]);
        O[2] = fma2(pk2(w1.x, w1.y), S1, O[2]);
        O[3] = fma2(pk2(w1.z, w1.w), S1, O[3]);
    }
    #pragma unroll
    for (int j = 0; j < 3; j++) {
        int c = C_ + j;
        float4 na = sxp[j * 4], nbv = sxp[j * 4 + 1];
        f32x2_t A0 = pk2(na.x, na.y),  A1 = pk2(na.z, na.w);
        f32x2_t A2 = pk2(nbv.x, nbv.y), A3 = pk2(nbv.z, nbv.w);
        f32x2_t t0 = fma2(P[1], A1, mul2(P[0], A0));
        f32x2_t u0 = fma2(P[3], A3, mul2(P[2], A2));
        f32x2_t t1 = fma2(P[5], A1, mul2(P[4], A0));
        f32x2_t u1 = fma2(P[7], A3, mul2(P[6], A2));
        float sp0 = hsum2(t0) + hsum2(u0);
        float sp1 = hsum2(t1) + hsum2(u1);
        float s0 = sp0 + __shfl_xor_sync(0xffffffffu, sp0, 4);
        float s1 = sp1 + __shfl_xor_sync(0xffffffffu, sp1, 4);
        f32x2_t S0 = pk2(s0, s0), S1 = pk2(s1, s1);
        float4 w0 = WvT[c * 16 + wb];
        float4 w1 = WvT[c * 16 + 8 + wb];
        O[0] = fma2(pk2(w0.x, w0.y), S0, O[0]);
        O[1] = fma2(pk2(w0.z, w0.w), S0, O[1]);
        O[2] = fma2(pk2(w1.x, w1.y), S1, O[2]);
        O[3] = fma2(pk2(w1.z, w1.w), S1, O[3]);
    }

    // ---- store: out[b, (2hh+j)*8 + kh*4 + dd, n]
    {
        float o[8];
        #pragma unroll
        for (int d = 0; d < 4; d++) upk2(O[d], o[2 * d], o[2 * d + 1]);
        float* ob0 = out + ((size_t)(b * C_ + (2 * hh) * 8 + kh * 4)) * N_ + n;
        float* ob1 = out + ((size_t)(b * C_ + (2 * hh + 1) * 8 + kh * 4)) * N_ + n;
        #pragma unroll
        for (int dd = 0; dd < 4; dd++) {
            ob0[(size_t)dd * N_] = o[dd];
            ob1[(size_t)dd * N_] = o[4 + dd];
        }
    }
}

extern "C" void kernel_launch(void* const* d_in, const int* in_sizes, int n_in,
                              void* d_out, int out_size)
{
    (void)in_sizes; (void)n_in; (void)out_size;
    const float* pcd       = (const float*)d_in[0];
    const float* neighbors = (const float*)d_in[1];
    const float* xyz       = (const float*)d_in[2];
    const float* Wq        = (const float*)d_in[3];
    const float* Wk        = (const float*)d_in[4];
    const float* Wv        = (const float*)d_in[5];
    const int*   idx_all   = (const int*)d_in[6];
    float* out = (float*)d_out;

    permute_w_kernel<<<(W_ELEMS + 255) / 256, 256>>>(Wq, Wk, Wv);

    const int grid = (B_ * N_) / PTS;   // 2048
    pt_attn_kernel<<<grid, THREADS>>>(pcd, neighbors, xyz, idx_all, out);
}

// round 17
// speedup vs baseline: 1.1779x; 1.0609x over previous
#include <cuda_runtime.h>
#include <math.h>

// Pe_i_CrossAttention: fused point-transformer local attention.
// B=4, C=64, N=16384, K=16, H=8, D=8.
// R17: R16 (warp = 4 pts, lane = (p, kh, hh), W smem quad-permuted, f32x2
// FMA) + latency coverage: unroll-4 in passes 2/3 (deeper LDG batching)
// and REVERSED c-order in pass 3 (tail of pass-2 footprint is L1-hot).
// energy[h,k] = (Wk_h^T q_h).nb_k ; out[h] = Wv_h @ (sum_k attn_k nb_k)

#define B_      4
#define C_      64
#define N_      16384
#define K_      16
#define CP3     67
#define PTS     32                  // 8 warps x 4 points
#define THREADS 256
#define PC_STRIDE 68
#define SX_STRIDE 52
#define W_ELEMS (CP3 * C_)          // 4288
#define CSTR    ((size_t)N_ * K_)   // float stride between c-rows of neighbors

typedef unsigned long long f32x2_t;

__device__ __forceinline__ f32x2_t pk2(float lo, float hi) {
    f32x2_t r; asm("mov.b64 %0, {%1, %2};" : "=l"(r) : "f"(lo), "f"(hi)); return r;
}
__device__ __forceinline__ void upk2(f32x2_t a, float& lo, float& hi) {
    asm("mov.b64 {%0, %1}, %2;" : "=f"(lo), "=f"(hi) : "l"(a));
}
__device__ __forceinline__ f32x2_t fma2(f32x2_t a, f32x2_t b, f32x2_t c) {
    f32x2_t d; asm("fma.rn.f32x2 %0, %1, %2, %3;" : "=l"(d) : "l"(a), "l"(b), "l"(c));
    return d;
}
__device__ __forceinline__ f32x2_t mul2(f32x2_t a, f32x2_t b) {
    f32x2_t d; asm("mul.rn.f32x2 %0, %1, %2;" : "=l"(d) : "l"(a), "l"(b));
    return d;
}
__device__ __forceinline__ float hsum2(f32x2_t a) {
    float x, y; upk2(a, x, y); return x + y;
}

__device__ __align__(16) float g_WT[3 * W_ELEMS];

// Quad-permuted transpose:
//   source element: W[o*67 + c], o = h*8 + d;  dd = d&3, kh = (d>>2)
//   dest: [c][new_pos][dd], new_pos = (h&1)*8 + (h>>1)*2 + kh
// -> in-kernel instr j (head 2hh+j) reads float4 at c*16 + j*8 + hh*2 + kh:
//    8 unique float4 per instr, contiguous 128B -> 1 conflict-free wavefront.
// 1/sqrt(D) folded into Wq.
__global__ void permute_w_kernel(const float* __restrict__ Wq,
                                 const float* __restrict__ Wk,
                                 const float* __restrict__ Wv)
{
    int e = blockIdx.x * blockDim.x + threadIdx.x;
    if (e >= W_ELEMS) return;
    int c    = e >> 6;
    int t    = e & 63;
    int qidx = t >> 2;              // 0..15
    int dd   = t & 3;
    int h    = qidx >> 1;
    int kh   = qidx & 1;
    int o    = h * 8 + kh * 4 + dd;
    int np   = (h & 1) * 8 + (h >> 1) * 2 + kh;
    int dst  = c * 64 + np * 4 + dd;
    g_WT[dst]               = Wq[o * CP3 + c] * 0.35355339059327373f;
    g_WT[W_ELEMS + dst]     = Wk[o * CP3 + c];
    g_WT[2 * W_ELEMS + dst] = Wv[o * CP3 + c];
}

__global__ __launch_bounds__(THREADS, 3)
void pt_attn_kernel(const float* __restrict__ pcd,
                    const float* __restrict__ neighbors,
                    const float* __restrict__ xyz,
                    const int*   __restrict__ idx_all,
                    float*       __restrict__ out)
{
    __shared__ __align__(16) float sW[3 * W_ELEMS];          // 51456 B
    __shared__ float pc[PTS * PC_STRIDE];                    // [32][68]
    __shared__ __align__(16) float sxyz[PTS * SX_STRIDE];    // [32][52] (3x16 used)

    const int tid = threadIdx.x;
    const int g0  = blockIdx.x * PTS;         // 32 | 16384 -> never crosses batch
    const int b   = g0 / N_;
    const int n0  = g0 % N_;

    // ---- W: coalesced float4 copy from pre-permuted global scratch
    {
        const float4* src = (const float4*)g_WT;
        float4*       dst = (float4*)sW;
        for (int e = tid; e < 3 * W_ELEMS / 4; e += THREADS) dst[e] = src[e];
    }
    // ---- center features (coalesced over p, 32-wide)
    for (int e = tid; e < C_ * PTS; e += THREADS) {
        int c = e >> 5, p = e & 31;
        pc[p * PC_STRIDE + c] = pcd[(b * C_ + c) * N_ + n0 + p];
    }
    for (int e = tid; e < 3 * PTS; e += THREADS) {
        int j = e >> 5, p = e & 31;
        pc[p * PC_STRIDE + 64 + j] = xyz[(b * 3 + j) * N_ + n0 + p];
    }
    // ---- gathered xyz rows (xyz is 768 KB -> L2-resident)
    for (int e = tid; e < PTS * K_; e += THREADS) {
        int p = e >> 4, k = e & 15;
        int idx = idx_all[(b * N_ + n0 + p) * K_ + k];
        #pragma unroll
        for (int j = 0; j < 3; j++)
            sxyz[p * SX_STRIDE + j * 16 + k] = xyz[(b * 3 + j) * N_ + idx];
    }
    __syncthreads();

    // ---- lane mapping
    const int lane = tid & 31;
    const int w    = tid >> 5;
    const int p    = lane >> 3;               // point within warp (0..3)
    const int kh   = (lane >> 2) & 1;         // k-half / d-half
    const int hh   = lane & 3;                // head-pair index
    const int pidx = w * 4 + p;
    const int n    = n0 + pidx;
    const int wb   = hh * 2 + kh;             // W float4 sub-offset
    const float*  pcp = pc + pidx * PC_STRIDE;
    const float4* sxp = (const float4*)(sxyz + pidx * SX_STRIDE + kh * 8);
    const float*  nbg = neighbors + ((size_t)(b * C_) * N_ + (size_t)n) * K_ + kh * 8;
    const float4* WqT = (const float4*)sW;                    // [c][16] float4
    const float4* WkT = (const float4*)(sW + W_ELEMS);
    const float4* WvT = (const float4*)(sW + 2 * W_ELEMS);

    // ======== pass 1: q (packed pairs; scale pre-folded) ========
    f32x2_t Q01 = 0, Q23 = 0, Q45 = 0, Q67 = 0;
    #pragma unroll 4
    for (int c = 0; c < CP3; c++) {
        float x = pcp[c];
        f32x2_t X = pk2(x, x);
        float4 w0 = WqT[c * 16 + wb];
        float4 w1 = WqT[c * 16 + 8 + wb];
        Q01 = fma2(pk2(w0.x, w0.y), X, Q01);
        Q23 = fma2(pk2(w0.z, w0.w), X, Q23);
        Q45 = fma2(pk2(w1.x, w1.y), X, Q45);
        Q67 = fma2(pk2(w1.z, w1.w), X, Q67);
    }

    // ======== pass 2: energies (packed) over own 8 k for 2 heads ========
    f32x2_t E[8];
    #pragma unroll
    for (int k = 0; k < 8; k++) E[k] = 0;
    #pragma unroll 4
    for (int c = 0; c < C_; c++) {
        const float4* nr = (const float4*)(nbg + (size_t)c * CSTR);
        float4 na = nr[0], nbv = nr[1];
        float4 w0 = WkT[c * 16 + wb];
        float4 w1 = WkT[c * 16 + 8 + wb];
        float rp0 = hsum2(fma2(pk2(w0.z, w0.w), Q23, mul2(pk2(w0.x, w0.y), Q01)));
        float rp1 = hsum2(fma2(pk2(w1.z, w1.w), Q67, mul2(pk2(w1.x, w1.y), Q45)));
        float r0 = rp0 + __shfl_xor_sync(0xffffffffu, rp0, 4);
        float r1 = rp1 + __shfl_xor_sync(0xffffffffu, rp1, 4);
        f32x2_t R0 = pk2(r0, r0), R1 = pk2(r1, r1);
        f32x2_t A0 = pk2(na.x, na.y),  A1 = pk2(na.z, na.w);
        f32x2_t A2 = pk2(nbv.x, nbv.y), A3 = pk2(nbv.z, nbv.w);
        E[0] = fma2(R0, A0, E[0]); E[1] = fma2(R0, A1, E[1]);
        E[2] = fma2(R0, A2, E[2]); E[3] = fma2(R0, A3, E[3]);
        E[4] = fma2(R1, A0, E[4]); E[5] = fma2(R1, A1, E[5]);
        E[6] = fma2(R1, A2, E[6]); E[7] = fma2(R1, A3, E[7]);
    }
    #pragma unroll
    for (int j = 0; j < 3; j++) {             // xyz tail rows from smem
        int c = C_ + j;
        float4 na = sxp[j * 4], nbv = sxp[j * 4 + 1];
        float4 w0 = WkT[c * 16 + wb];
        float4 w1 = WkT[c * 16 + 8 + wb];
        float rp0 = hsum2(fma2(pk2(w0.z, w0.w), Q23, mul2(pk2(w0.x, w0.y), Q01)));
        float rp1 = hsum2(fma2(pk2(w1.z, w1.w), Q67, mul2(pk2(w1.x, w1.y), Q45)));
        float r0 = rp0 + __shfl_xor_sync(0xffffffffu, rp0, 4);
        float r1 = rp1 + __shfl_xor_sync(0xffffffffu, rp1, 4);
        f32x2_t R0 = pk2(r0, r0), R1 = pk2(r1, r1);
        f32x2_t A0 = pk2(na.x, na.y),  A1 = pk2(na.z, na.w);
        f32x2_t A2 = pk2(nbv.x, nbv.y), A3 = pk2(nbv.z, nbv.w);
        E[0] = fma2(R0, A0, E[0]); E[1] = fma2(R0, A1, E[1]);
        E[2] = fma2(R0, A2, E[2]); E[3] = fma2(R0, A3, E[3]);
        E[4] = fma2(R1, A0, E[4]); E[5] = fma2(R1, A1, E[5]);
        E[6] = fma2(R1, A2, E[6]); E[7] = fma2(R1, A3, E[7]);
    }

    // ======== softmax per head over 16 k (8 local + kh-partner) ========
    float e0[16];
    #pragma unroll
    for (int k = 0; k < 8; k++) upk2(E[k], e0[2 * k], e0[2 * k + 1]);
    float m0 = e0[0], m1 = e0[8];
    #pragma unroll
    for (int k = 1; k < 8; k++) { m0 = fmaxf(m0, e0[k]); m1 = fmaxf(m1, e0[8 + k]); }
    m0 = fmaxf(m0, __shfl_xor_sync(0xffffffffu, m0, 4));
    m1 = fmaxf(m1, __shfl_xor_sync(0xffffffffu, m1, 4));
    float s0sum = 0.f, s1sum = 0.f;
    #pragma unroll
    for (int k = 0; k < 8; k++) {
        e0[k]     = __expf(e0[k] - m0);     s0sum += e0[k];
        e0[8 + k] = __expf(e0[8 + k] - m1); s1sum += e0[8 + k];
    }
    s0sum += __shfl_xor_sync(0xffffffffu, s0sum, 4);
    s1sum += __shfl_xor_sync(0xffffffffu, s1sum, 4);
    float inv0 = 1.f / s0sum, inv1 = 1.f / s1sum;
    #pragma unroll
    for (int k = 0; k < 8; k++) { e0[k] *= inv0; e0[8 + k] *= inv1; }
    f32x2_t P[8];
    #pragma unroll
    for (int k = 0; k < 8; k++) P[k] = pk2(e0[2 * k], e0[2 * k + 1]);

    // ======== pass 3: o (packed) += Wv * s; REVERSE c order so the tail of
    // pass-2's nb footprint (most recently used lines) hits L1 first ========
    f32x2_t O[4];
    #pragma unroll
    for (int d = 0; d < 4; d++) O[d] = 0;
    #pragma unroll
    for (int j = 2; j >= 0; j--) {            // xyz tail rows first (smem)
        int c = C_ + j;
        float4 na = sxp[j * 4], nbv = sxp[j * 4 + 1];
        f32x2_t A0 = pk2(na.x, na.y),  A1 = pk2(na.z, na.w);
        f32x2_t A2 = pk2(nbv.x, nbv.y), A3 = pk2(nbv.z, nbv.w);
        f32x2_t t0 = fma2(P[1], A1, mul2(P[0], A0));
        f32x2_t u0 = fma2(P[3], A3, mul2(P[2], A2));
        f32x2_t t1 = fma2(P[5], A1, mul2(P[4], A0));
        f32x2_t u1 = fma2(P[7], A3, mul2(P[6], A2));
        float sp0 = hsum2(t0) + hsum2(u0);
        float sp1 = hsum2(t1) + hsum2(u1);
        float s0 = sp0 + __shfl_xor_sync(0xffffffffu, sp0, 4);
        float s1 = sp1 + __shfl_xor_sync(0xffffffffu, sp1, 4);
        f32x2_t S0 = pk2(s0, s0), S1 = pk2(s1, s1);
        float4 w0 = WvT[c * 16 + wb];
        float4 w1 = WvT[c * 16 + 8 + wb];
        O[0] = fma2(pk2(w0.x, w0.y), S0, O[0]);
        O[1] = fma2(pk2(w0.z, w0.w), S0, O[1]);
        O[2] = fma2(pk2(w1.x, w1.y), S1, O[2]);
        O[3] = fma2(pk2(w1.z, w1.w), S1, O[3]);
    }
    #pragma unroll 4
    for (int c = C_ - 1; c >= 0; c--) {
        const float4* nr = (const float4*)(nbg + (size_t)c * CSTR);
        float4 na = nr[0], nbv = nr[1];
        f32x2_t A0 = pk2(na.x, na.y),  A1 = pk2(na.z, na.w);
        f32x2_t A2 = pk2(nbv.x, nbv.y), A3 = pk2(nbv.z, nbv.w);
        f32x2_t t0 = fma2(P[1], A1, mul2(P[0], A0));
        f32x2_t u0 = fma2(P[3], A3, mul2(P[2], A2));
        f32x2_t t1 = fma2(P[5], A1, mul2(P[4], A0));
        f32x2_t u1 = fma2(P[7], A3, mul2(P[6], A2));
        float sp0 = hsum2(t0) + hsum2(u0);
        float sp1 = hsum2(t1) + hsum2(u1);
        float s0 = sp0 + __shfl_xor_sync(0xffffffffu, sp0, 4);
        float s1 = sp1 + __shfl_xor_sync(0xffffffffu, sp1, 4);
        f32x2_t S0 = pk2(s0, s0), S1 = pk2(s1, s1);
        float4 w0 = WvT[c * 16 + wb];
        float4 w1 = WvT[c * 16 + 8 + wb];
        O[0] = fma2(pk2(w0.x, w0.y), S0, O[0]);
        O[1] = fma2(pk2(w0.z, w0.w), S0, O[1]);
        O[2] = fma2(pk2(w1.x, w1.y), S1, O[2]);
        O[3] = fma2(pk2(w1.z, w1.w), S1, O[3]);
    }

    // ---- store: out[b, (2hh+j)*8 + kh*4 + dd, n]
    {
        float o[8];
        #pragma unroll
        for (int d = 0; d < 4; d++) upk2(O[d], o[2 * d], o[2 * d + 1]);
        float* ob0 = out + ((size_t)(b * C_ + (2 * hh) * 8 + kh * 4)) * N_ + n;
        float* ob1 = out + ((size_t)(b * C_ + (2 * hh + 1) * 8 + kh * 4)) * N_ + n;
        #pragma unroll
        for (int dd = 0; dd < 4; dd++) {
            ob0[(size_t)dd * N_] = o[dd];
            ob1[(size_t)dd * N_] = o[4 + dd];
        }
    }
}

extern "C" void kernel_launch(void* const* d_in, const int* in_sizes, int n_in,
                              void* d_out, int out_size)
{
    (void)in_sizes; (void)n_in; (void)out_size;
    const float* pcd       = (const float*)d_in[0];
    const float* neighbors = (const float*)d_in[1];
    const float* xyz       = (const float*)d_in[2];
    const float* Wq        = (const float*)d_in[3];
    const float* Wk        = (const float*)d_in[4];
    const float* Wv        = (const float*)d_in[5];
    const int*   idx_all   = (const int*)d_in[6];
    float* out = (float*)d_out;

    permute_w_kernel<<<(W_ELEMS + 255) / 256, 256>>>(Wq, Wk, Wv);

    const int grid = (B_ * N_) / PTS;   // 2048
    pt_attn_kernel<<<grid, THREADS>>>(pcd, neighbors, xyz, idx_all, out);
}